// round 1
// baseline (speedup 1.0000x reference)
#include <cuda_runtime.h>
#include <math.h>

// Problem constants (fixed by the reference: x [8,2048,1024], W [3072,1024])
#define BATCH   8
#define SEQ     2048
#define EMBED   1024
#define QKVD    3072   // 3 * EMBED

// Scratch: device globals (no allocations allowed in kernel_launch)
__device__ float g_qkv[(size_t)BATCH * SEQ * QKVD];     // 201 MB: [b, n, 3E]
__device__ float g_scores[(size_t)BATCH * SEQ * SEQ];   // 134 MB: [b, q, k]

// ---------------------------------------------------------------------------
// Tiled fp32 GEMM.
//   TRANS_B = true : C[m,n] = alpha * sum_k A[m,k] * B[n,k]   (A @ B^T)
//   TRANS_B = false: C[m,n] = alpha * sum_k A[m,k] * B[k,n]   (A @ B)
// Block tile 128x128, K-tile 8, 256 threads, 8x8 per-thread microtile.
// All dims here are exact multiples of the tiles; no bounds checks.
// blockIdx.z = batch index with the given pointer strides.
// ---------------------------------------------------------------------------
template<bool TRANS_B, bool HAS_BIAS>
__launch_bounds__(256, 2)
__global__ void sgemm_kernel(const float* __restrict__ A,
                             const float* __restrict__ Bp,
                             const float* __restrict__ bias,
                             float* __restrict__ C,
                             int K, int lda, int ldb, int ldc,
                             long long sA, long long sB, long long sC,
                             float alpha)
{
    __shared__ float As[8][128];
    __shared__ float Bs[8][128];

    const int tid = threadIdx.x;
    const float* Ab = A  + (size_t)blockIdx.z * sA;
    const float* Bb = Bp + (size_t)blockIdx.z * sB;
    float*       Cb = C  + (size_t)blockIdx.z * sC;

    const int rowBlock = blockIdx.y * 128;
    const int colBlock = blockIdx.x * 128;

    // A tile loader: 128 rows x 8 cols, 2 threads/row, one float4 each
    const int arow = tid >> 1;
    const int acol = (tid & 1) * 4;
    // B tile loader
    int brow, bcol;
    if (TRANS_B) { brow = tid >> 1;  bcol = (tid & 1) * 4;  }   // 128 n-rows x 8 k-cols
    else         { brow = tid >> 5;  bcol = (tid & 31) * 4; }   // 8 k-rows x 128 n-cols

    const int ty = tid >> 4;   // 0..15
    const int tx = tid & 15;   // 0..15

    float acc[8][8];
    #pragma unroll
    for (int i = 0; i < 8; ++i)
        #pragma unroll
        for (int j = 0; j < 8; ++j) acc[i][j] = 0.0f;

    const float* Aptr = Ab + (size_t)(rowBlock + arow) * lda + acol;
    const float* Bptr = TRANS_B
        ? Bb + (size_t)(colBlock + brow) * ldb + bcol
        : Bb + (size_t)brow * ldb + colBlock + bcol;

    for (int k0 = 0; k0 < K; k0 += 8) {
        // issue global loads first, then drain previous compute
        const float4 a4 = *reinterpret_cast<const float4*>(Aptr + k0);
        float4 b4;
        if (TRANS_B) b4 = *reinterpret_cast<const float4*>(Bptr + k0);
        else         b4 = *reinterpret_cast<const float4*>(Bptr + (size_t)k0 * ldb);

        __syncthreads();
        As[acol + 0][arow] = a4.x;
        As[acol + 1][arow] = a4.y;
        As[acol + 2][arow] = a4.z;
        As[acol + 3][arow] = a4.w;
        if (TRANS_B) {
            Bs[bcol + 0][brow] = b4.x;
            Bs[bcol + 1][brow] = b4.y;
            Bs[bcol + 2][brow] = b4.z;
            Bs[bcol + 3][brow] = b4.w;
        } else {
            *reinterpret_cast<float4*>(&Bs[brow][bcol]) = b4;
        }
        __syncthreads();

        #pragma unroll
        for (int kk = 0; kk < 8; ++kk) {
            float a[8], b[8];
            #pragma unroll
            for (int i = 0; i < 8; ++i) a[i] = As[kk][ty * 8 + i];
            #pragma unroll
            for (int j = 0; j < 8; ++j) b[j] = Bs[kk][tx * 8 + j];
            #pragma unroll
            for (int i = 0; i < 8; ++i)
                #pragma unroll
                for (int j = 0; j < 8; ++j)
                    acc[i][j] = fmaf(a[i], b[j], acc[i][j]);
        }
    }

    // Epilogue: scale (+ optional bias), vectorized stores
    #pragma unroll
    for (int i = 0; i < 8; ++i) {
        const int r = rowBlock + ty * 8 + i;
        float* cp = Cb + (size_t)r * ldc + colBlock + tx * 8;
        #pragma unroll
        for (int j = 0; j < 8; j += 4) {
            float4 o;
            o.x = acc[i][j + 0] * alpha;
            o.y = acc[i][j + 1] * alpha;
            o.z = acc[i][j + 2] * alpha;
            o.w = acc[i][j + 3] * alpha;
            if (HAS_BIAS) {
                const int c = colBlock + tx * 8 + j;
                o.x += bias[c + 0];
                o.y += bias[c + 1];
                o.z += bias[c + 2];
                o.w += bias[c + 3];
            }
            *reinterpret_cast<float4*>(cp + j) = o;
        }
    }
}

// ---------------------------------------------------------------------------
// Row softmax over SEQ=2048 columns. One CTA per row; row cached in smem.
// ---------------------------------------------------------------------------
__global__ void softmax_kernel(float* __restrict__ s)
{
    __shared__ float row[SEQ];
    __shared__ float red[8];

    const int tid = threadIdx.x;
    float* p = s + (size_t)blockIdx.x * SEQ;
    float4* p4 = reinterpret_cast<float4*>(p);
    float4* r4 = reinterpret_cast<float4*>(row);

    // pass 1: load + max
    float lmax = -3.4e38f;
    #pragma unroll
    for (int it = 0; it < 2; ++it) {
        const float4 t = p4[tid + it * 256];
        r4[tid + it * 256] = t;
        lmax = fmaxf(lmax, fmaxf(fmaxf(t.x, t.y), fmaxf(t.z, t.w)));
    }
    #pragma unroll
    for (int o = 16; o; o >>= 1) lmax = fmaxf(lmax, __shfl_xor_sync(0xffffffffu, lmax, o));
    if ((tid & 31) == 0) red[tid >> 5] = lmax;
    __syncthreads();
    const float rmax = fmaxf(fmaxf(fmaxf(red[0], red[1]), fmaxf(red[2], red[3])),
                             fmaxf(fmaxf(red[4], red[5]), fmaxf(red[6], red[7])));
    __syncthreads();  // protect red[] reuse

    // pass 2: exp + sum
    float lsum = 0.0f;
    #pragma unroll
    for (int it = 0; it < 2; ++it) {
        float4 t = r4[tid + it * 256];
        t.x = expf(t.x - rmax);
        t.y = expf(t.y - rmax);
        t.z = expf(t.z - rmax);
        t.w = expf(t.w - rmax);
        r4[tid + it * 256] = t;
        lsum += (t.x + t.y) + (t.z + t.w);
    }
    #pragma unroll
    for (int o = 16; o; o >>= 1) lsum += __shfl_xor_sync(0xffffffffu, lsum, o);
    if ((tid & 31) == 0) red[tid >> 5] = lsum;
    __syncthreads();
    const float rsum = ((red[0] + red[1]) + (red[2] + red[3])) +
                       ((red[4] + red[5]) + (red[6] + red[7]));
    const float inv = 1.0f / rsum;

    // pass 3: normalize + store
    #pragma unroll
    for (int it = 0; it < 2; ++it) {
        float4 t = r4[tid + it * 256];
        t.x *= inv; t.y *= inv; t.z *= inv; t.w *= inv;
        p4[tid + it * 256] = t;
    }
}

// ---------------------------------------------------------------------------
extern "C" void kernel_launch(void* const* d_in, const int* in_sizes, int n_in,
                              void* d_out, int out_size)
{
    const float* x = (const float*)d_in[0];   // [8, 2048, 1024]
    const float* W = (const float*)d_in[1];   // [3072, 1024]
    const float* b = (const float*)d_in[2];   // [3072]
    float* out = (float*)d_out;               // [8, 2048, 1024]

    float *qkv, *sc;
    { void* p; cudaGetSymbolAddress(&p, g_qkv);    qkv = (float*)p; }
    { void* p; cudaGetSymbolAddress(&p, g_scores); sc  = (float*)p; }

    // 1) QKV = x @ W^T + b   : M=16384, N=3072, K=1024
    sgemm_kernel<true, true><<<dim3(QKVD / 128, (BATCH * SEQ) / 128, 1), 256>>>(
        x, W, b, qkv,
        EMBED, /*lda*/EMBED, /*ldb*/EMBED, /*ldc*/QKVD,
        0, 0, 0, 1.0f);

    // 2) scores = Q @ K^T * (1/sqrt(E))  per batch : M=N=2048, K=1024
    sgemm_kernel<true, false><<<dim3(SEQ / 128, SEQ / 128, BATCH), 256>>>(
        qkv /*Q*/, qkv + EMBED /*K*/, nullptr, sc,
        EMBED, /*lda*/QKVD, /*ldb*/QKVD, /*ldc*/SEQ,
        (long long)SEQ * QKVD, (long long)SEQ * QKVD, (long long)SEQ * SEQ,
        0.03125f /* 1/32 */);

    // 3) row-wise softmax over scores
    softmax_kernel<<<BATCH * SEQ, 256>>>(sc);

    // 4) out = attn @ V   per batch : M=2048, N=1024, K=2048
    sgemm_kernel<false, false><<<dim3(EMBED / 128, SEQ / 128, BATCH), 256>>>(
        sc, qkv + 2 * EMBED /*V*/, nullptr, out,
        SEQ, /*lda*/SEQ, /*ldb*/QKVD, /*ldc*/EMBED,
        (long long)SEQ * SEQ, (long long)SEQ * QKVD, (long long)SEQ * EMBED,
        1.0f);
}

// round 3
// speedup vs baseline: 1.8521x; 1.8521x over previous
#include <cuda_runtime.h>
#include <cuda_bf16.h>
#include <math.h>
#include <stdint.h>

#define BATCH   8
#define SEQ     2048
#define EMBED   1024
#define QKVD    3072

// ---------------- scratch (device globals; no allocs allowed) ---------------
__device__ float         g_qkv   [(size_t)BATCH * SEQ * QKVD];
__device__ float         g_scores[(size_t)BATCH * SEQ * SEQ];
__device__ __nv_bfloat16 g_A1[(size_t)BATCH * SEQ * (3*EMBED)];   // x split  (A-order)
__device__ __nv_bfloat16 g_B1[(size_t)QKVD * (3*EMBED)];          // W split  (B-order)
__device__ __nv_bfloat16 g_QA[(size_t)BATCH * SEQ * (3*EMBED)];   // Q split  (A-order)
__device__ __nv_bfloat16 g_KB[(size_t)BATCH * SEQ * (3*EMBED)];   // K split  (B-order)
__device__ __nv_bfloat16 g_VB[(size_t)BATCH * EMBED * (3*SEQ)];   // V^T split (B-order)
__device__ __nv_bfloat16 g_PA[(size_t)BATCH * SEQ * (3*SEQ)];     // probs split (A-order)

// ---------------- asm helpers ------------------------------------------------
__device__ __forceinline__ uint32_t smem_u32(const void* p) {
    uint32_t a;
    asm("{ .reg .u64 t; cvta.to.shared.u64 t, %1; cvt.u32.u64 %0, t; }" : "=r"(a) : "l"(p));
    return a;
}
#define CP_ASYNC16(dst, src) \
    asm volatile("cp.async.cg.shared.global [%0], [%1], 16;" :: "r"(dst), "l"(src))
#define CP_COMMIT() asm volatile("cp.async.commit_group;" ::: "memory")
#define CP_WAIT1()  asm volatile("cp.async.wait_group 1;"  ::: "memory")
#define LDMX4(r, addr) \
    asm volatile("ldmatrix.sync.aligned.m8n8.x4.shared.b16 {%0,%1,%2,%3}, [%4];" \
        : "=r"((r)[0]), "=r"((r)[1]), "=r"((r)[2]), "=r"((r)[3]) : "r"(addr))
#define MMA16816(d, a, b) \
    asm volatile("mma.sync.aligned.m16n8k16.row.col.f32.bf16.bf16.f32 " \
        "{%0,%1,%2,%3}, {%4,%5,%6,%7}, {%8,%9}, {%0,%1,%2,%3};" \
        : "+f"((d)[0]), "+f"((d)[1]), "+f"((d)[2]), "+f"((d)[3]) \
        : "r"((a)[0]), "r"((a)[1]), "r"((a)[2]), "r"((a)[3]), "r"((b)[0]), "r"((b)[1]))

// ---------------- tensor-core GEMM: C[m,n] = alpha*(sum_k A[m,k]B[n,k]) (+bias)
// A: bf16 [*, K] row-major; B: bf16 [*, K] row-major. Block tile 128x128,
// K-chunk 64, double-buffered cp.async. 256 threads = 8 warps (2m x 4n),
// warp tile 64x32, mma.m16n8k16 bf16 -> fp32.
#define LDT     72                       // smem row pitch in halves (144 B)
#define ATILE_H (128 * LDT)              // 9216 halves
#define BUF_H   (2 * ATILE_H)            // A+B per buffer
#define SMEM_B  (2 * BUF_H * 2)          // bytes: 73728

__device__ __forceinline__ void load_chunk(uint32_t sb, int buf,
    const __nv_bfloat16* __restrict__ Ag, const __nv_bfloat16* __restrict__ Bg,
    int K, int k0, int tid)
{
    const int r = tid >> 1;
    const int c = (tid & 1) * 32;
    const uint32_t base = sb + (uint32_t)buf * (BUF_H * 2) + (r * LDT + c) * 2;
    const __nv_bfloat16* as = Ag + (size_t)r * K + k0 + c;
    const __nv_bfloat16* bs = Bg + (size_t)r * K + k0 + c;
    #pragma unroll
    for (int i = 0; i < 4; ++i) CP_ASYNC16(base + i * 16, as + i * 8);
    #pragma unroll
    for (int i = 0; i < 4; ++i) CP_ASYNC16(base + ATILE_H * 2 + i * 16, bs + i * 8);
}

template<bool HAS_BIAS>
__global__ void __launch_bounds__(256, 2) mma_gemm(
    const __nv_bfloat16* __restrict__ A, const __nv_bfloat16* __restrict__ B,
    const float* __restrict__ bias, float* __restrict__ C,
    int K, int ldc, long long sA, long long sB, long long sC, float alpha)
{
    extern __shared__ char smem[];
    const uint32_t sb = smem_u32(smem);
    const int tid = threadIdx.x;
    const int lane = tid & 31;
    const int wid = tid >> 5;
    const int wm = (wid & 1) * 64;        // warp m offset in tile
    const int wn = (wid >> 1) * 32;       // warp n offset in tile

    const __nv_bfloat16* Ag = A + blockIdx.z * sA + (size_t)(blockIdx.y * 128) * K;
    const __nv_bfloat16* Bg = B + blockIdx.z * sB + (size_t)(blockIdx.x * 128) * K;
    float* Cg = C + blockIdx.z * sC;

    // ldmatrix per-lane source rows
    const int ar = (lane & 7) + ((lane >> 3) & 1) * 8;   // A row within 16
    const int ak = (lane >> 4) * 8;                      // A k-half
    const int bn = (lane & 7) + ((lane >> 4) & 1) * 8;   // B n within 16
    const int bk = ((lane >> 3) & 1) * 8;                // B k-half

    float acc[4][4][4];
    #pragma unroll
    for (int i = 0; i < 4; ++i)
        #pragma unroll
        for (int j = 0; j < 4; ++j)
            #pragma unroll
            for (int q = 0; q < 4; ++q) acc[i][j][q] = 0.0f;

    const int nch = K / 64;
    load_chunk(sb, 0, Ag, Bg, K, 0, tid);  CP_COMMIT();
    load_chunk(sb, 1, Ag, Bg, K, 64, tid); CP_COMMIT();

    for (int ch = 0; ch < nch; ++ch) {
        const int buf = ch & 1;
        CP_WAIT1();
        __syncthreads();

        const uint32_t abase = sb + (uint32_t)buf * (BUF_H * 2);
        const uint32_t bbase = abase + ATILE_H * 2;
        #pragma unroll
        for (int s = 0; s < 4; ++s) {
            uint32_t a[4][4];
            #pragma unroll
            for (int mf = 0; mf < 4; ++mf)
                LDMX4(a[mf], abase + ((wm + mf * 16 + ar) * LDT + s * 16 + ak) * 2);
            uint32_t b[2][4];
            #pragma unroll
            for (int n2 = 0; n2 < 2; ++n2)
                LDMX4(b[n2], bbase + ((wn + n2 * 16 + bn) * LDT + s * 16 + bk) * 2);
            #pragma unroll
            for (int mf = 0; mf < 4; ++mf)
                #pragma unroll
                for (int nf = 0; nf < 4; ++nf)
                    MMA16816(acc[mf][nf], a[mf], &b[nf >> 1][(nf & 1) * 2]);
        }
        __syncthreads();
        if (ch + 2 < nch) load_chunk(sb, buf, Ag, Bg, K, (ch + 2) * 64, tid);
        CP_COMMIT();   // always commit so wait_group 1 tracks the current chunk
    }

    // epilogue
    const int g  = lane >> 2;
    const int tg = lane & 3;
    #pragma unroll
    for (int mf = 0; mf < 4; ++mf) {
        const int row0 = blockIdx.y * 128 + wm + mf * 16 + g;
        #pragma unroll
        for (int nf = 0; nf < 4; ++nf) {
            const int col = blockIdx.x * 128 + wn + nf * 8 + tg * 2;
            float2 v0 = make_float2(acc[mf][nf][0] * alpha, acc[mf][nf][1] * alpha);
            float2 v1 = make_float2(acc[mf][nf][2] * alpha, acc[mf][nf][3] * alpha);
            if (HAS_BIAS) {
                const float2 bb = *reinterpret_cast<const float2*>(bias + col);
                v0.x += bb.x; v0.y += bb.y; v1.x += bb.x; v1.y += bb.y;
            }
            *reinterpret_cast<float2*>(Cg + (size_t)row0 * ldc + col) = v0;
            *reinterpret_cast<float2*>(Cg + (size_t)(row0 + 8) * ldc + col) = v1;
        }
    }
}

// ---------------- fp32 -> bf16 hi/lo split -----------------------------------
// dst [rows, 3K]: AORDER -> [hi|lo|hi], else -> [hi|hi|lo]
template<bool AORDER>
__global__ void split_kernel(const float* __restrict__ src, __nv_bfloat16* __restrict__ dst,
                             int K, int srcPitch, int srcOff, long long nvec)
{
    long long i = blockIdx.x * (long long)blockDim.x + threadIdx.x;
    if (i >= nvec) return;
    long long e = i * 4;
    int row = (int)(e / K), col = (int)(e % K);
    const float4 v = *reinterpret_cast<const float4*>(src + (size_t)row * srcPitch + srcOff + col);
    float vs[4] = { v.x, v.y, v.z, v.w };
    __nv_bfloat16 h[4], l[4];
    #pragma unroll
    for (int j = 0; j < 4; ++j) {
        h[j] = __float2bfloat16(vs[j]);
        l[j] = __float2bfloat16(vs[j] - __bfloat162float(h[j]));
    }
    __nv_bfloat162 hp0(h[0], h[1]), hp1(h[2], h[3]);
    __nv_bfloat162 lp0(l[0], l[1]), lp1(l[2], l[3]);
    __nv_bfloat16* d0 = dst + (size_t)row * 3 * K + col;
    reinterpret_cast<__nv_bfloat162*>(d0)[0] = hp0;
    reinterpret_cast<__nv_bfloat162*>(d0)[1] = hp1;
    if (AORDER) {
        reinterpret_cast<__nv_bfloat162*>(d0 + K)[0] = lp0;
        reinterpret_cast<__nv_bfloat162*>(d0 + K)[1] = lp1;
        reinterpret_cast<__nv_bfloat162*>(d0 + 2 * K)[0] = hp0;
        reinterpret_cast<__nv_bfloat162*>(d0 + 2 * K)[1] = hp1;
    } else {
        reinterpret_cast<__nv_bfloat162*>(d0 + K)[0] = hp0;
        reinterpret_cast<__nv_bfloat162*>(d0 + K)[1] = hp1;
        reinterpret_cast<__nv_bfloat162*>(d0 + 2 * K)[0] = lp0;
        reinterpret_cast<__nv_bfloat162*>(d0 + 2 * K)[1] = lp1;
    }
}

// ---------------- V transpose + split (B-order [hi|hi|lo]) -------------------
__global__ void vtrans_kernel(const float* __restrict__ qkv, __nv_bfloat16* __restrict__ VB)
{
    __shared__ float t[32][33];
    const int b = blockIdx.z;
    const int n0 = blockIdx.x * 32, e0 = blockIdx.y * 32;
    const int tx = threadIdx.x, ty = threadIdx.y;
    const float* src = qkv + (size_t)b * SEQ * QKVD + 2 * EMBED;
    #pragma unroll
    for (int i = 0; i < 4; ++i)
        t[ty + 8 * i][tx] = src[(size_t)(n0 + ty + 8 * i) * QKVD + e0 + tx];
    __syncthreads();
    __nv_bfloat16* dst = VB + (size_t)b * EMBED * (3 * SEQ);
    #pragma unroll
    for (int i = 0; i < 4; ++i) {
        const float v = t[tx][ty + 8 * i];
        const __nv_bfloat16 h = __float2bfloat16(v);
        const __nv_bfloat16 l = __float2bfloat16(v - __bfloat162float(h));
        const size_t base = (size_t)(e0 + ty + 8 * i) * (3 * SEQ) + n0 + tx;
        dst[base]           = h;
        dst[base + SEQ]     = h;
        dst[base + 2 * SEQ] = l;
    }
}

// ---------------- softmax + prob split (A-order [hi|lo|hi]) ------------------
__global__ void softmax_pa_kernel(const float* __restrict__ s, __nv_bfloat16* __restrict__ PA)
{
    __shared__ float row[SEQ];
    __shared__ float red[8];
    const int tid = threadIdx.x;
    const float4* p4 = reinterpret_cast<const float4*>(s + (size_t)blockIdx.x * SEQ);
    float4* r4 = reinterpret_cast<float4*>(row);

    float lmax = -3.4e38f;
    #pragma unroll
    for (int it = 0; it < 2; ++it) {
        const float4 t = p4[tid + it * 256];
        r4[tid + it * 256] = t;
        lmax = fmaxf(lmax, fmaxf(fmaxf(t.x, t.y), fmaxf(t.z, t.w)));
    }
    #pragma unroll
    for (int o = 16; o; o >>= 1) lmax = fmaxf(lmax, __shfl_xor_sync(0xffffffffu, lmax, o));
    if ((tid & 31) == 0) red[tid >> 5] = lmax;
    __syncthreads();
    const float rmax = fmaxf(fmaxf(fmaxf(red[0], red[1]), fmaxf(red[2], red[3])),
                             fmaxf(fmaxf(red[4], red[5]), fmaxf(red[6], red[7])));
    __syncthreads();

    float lsum = 0.0f;
    #pragma unroll
    for (int it = 0; it < 2; ++it) {
        float4 t = r4[tid + it * 256];
        t.x = expf(t.x - rmax); t.y = expf(t.y - rmax);
        t.z = expf(t.z - rmax); t.w = expf(t.w - rmax);
        r4[tid + it * 256] = t;
        lsum += (t.x + t.y) + (t.z + t.w);
    }
    #pragma unroll
    for (int o = 16; o; o >>= 1) lsum += __shfl_xor_sync(0xffffffffu, lsum, o);
    if ((tid & 31) == 0) red[tid >> 5] = lsum;
    __syncthreads();
    const float inv = 1.0f / (((red[0] + red[1]) + (red[2] + red[3])) +
                              ((red[4] + red[5]) + (red[6] + red[7])));

    __nv_bfloat16* pa = PA + (size_t)blockIdx.x * (3 * SEQ);
    #pragma unroll
    for (int it = 0; it < 2; ++it) {
        float4 t = r4[tid + it * 256];
        t.x *= inv; t.y *= inv; t.z *= inv; t.w *= inv;
        float vs[4] = { t.x, t.y, t.z, t.w };
        __nv_bfloat16 h[4], l[4];
        #pragma unroll
        for (int j = 0; j < 4; ++j) {
            h[j] = __float2bfloat16(vs[j]);
            l[j] = __float2bfloat16(vs[j] - __bfloat162float(h[j]));
        }
        const int idx = (tid + it * 256) * 4;
        __nv_bfloat162 hp0(h[0], h[1]), hp1(h[2], h[3]);
        __nv_bfloat162 lp0(l[0], l[1]), lp1(l[2], l[3]);
        reinterpret_cast<__nv_bfloat162*>(pa + idx)[0] = hp0;
        reinterpret_cast<__nv_bfloat162*>(pa + idx)[1] = hp1;
        reinterpret_cast<__nv_bfloat162*>(pa + SEQ + idx)[0] = lp0;
        reinterpret_cast<__nv_bfloat162*>(pa + SEQ + idx)[1] = lp1;
        reinterpret_cast<__nv_bfloat162*>(pa + 2 * SEQ + idx)[0] = hp0;
        reinterpret_cast<__nv_bfloat162*>(pa + 2 * SEQ + idx)[1] = hp1;
    }
}

// -----------------------------------------------------------------------------
extern "C" void kernel_launch(void* const* d_in, const int* in_sizes, int n_in,
                              void* d_out, int out_size)
{
    const float* x = (const float*)d_in[0];
    const float* W = (const float*)d_in[1];
    const float* b = (const float*)d_in[2];
    float* out = (float*)d_out;

    float *qkv, *sc;
    __nv_bfloat16 *A1, *B1, *QA, *KB, *VB, *PA;
    { void* p; cudaGetSymbolAddress(&p, g_qkv);    qkv = (float*)p; }
    { void* p; cudaGetSymbolAddress(&p, g_scores); sc  = (float*)p; }
    { void* p; cudaGetSymbolAddress(&p, g_A1); A1 = (__nv_bfloat16*)p; }
    { void* p; cudaGetSymbolAddress(&p, g_B1); B1 = (__nv_bfloat16*)p; }
    { void* p; cudaGetSymbolAddress(&p, g_QA); QA = (__nv_bfloat16*)p; }
    { void* p; cudaGetSymbolAddress(&p, g_KB); KB = (__nv_bfloat16*)p; }
    { void* p; cudaGetSymbolAddress(&p, g_VB); VB = (__nv_bfloat16*)p; }
    { void* p; cudaGetSymbolAddress(&p, g_PA); PA = (__nv_bfloat16*)p; }

    cudaFuncSetAttribute(mma_gemm<true>,  cudaFuncAttributeMaxDynamicSharedMemorySize, SMEM_B);
    cudaFuncSetAttribute(mma_gemm<false>, cudaFuncAttributeMaxDynamicSharedMemorySize, SMEM_B);

    const long long MN = (long long)BATCH * SEQ;   // 16384

    // splits: x -> A1 (A-order), W -> B1 (B-order)
    split_kernel<true ><<<(unsigned)((MN * EMBED / 4 + 255) / 256), 256>>>(
        x, A1, EMBED, EMBED, 0, MN * EMBED / 4);
    split_kernel<false><<<(unsigned)(((long long)QKVD * EMBED / 4 + 255) / 256), 256>>>(
        W, B1, EMBED, EMBED, 0, (long long)QKVD * EMBED / 4);

    // GEMM1: qkv = x @ W^T + b   (M=16384, N=3072, Keff=3072)
    mma_gemm<true><<<dim3(QKVD / 128, (unsigned)(MN / 128), 1), 256, SMEM_B>>>(
        A1, B1, b, qkv, 3 * EMBED, QKVD, 0, 0, 0, 1.0f);

    // Q -> QA (A-order), K -> KB (B-order), V -> VB (transpose, B-order)
    split_kernel<true ><<<(unsigned)((MN * EMBED / 4 + 255) / 256), 256>>>(
        qkv, QA, EMBED, QKVD, 0,     MN * EMBED / 4);
    split_kernel<false><<<(unsigned)((MN * EMBED / 4 + 255) / 256), 256>>>(
        qkv, KB, EMBED, QKVD, EMBED, MN * EMBED / 4);
    vtrans_kernel<<<dim3(SEQ / 32, EMBED / 32, BATCH), dim3(32, 8)>>>(qkv, VB);

    // GEMM2: scores = Q @ K^T / 32   (per batch M=N=2048, Keff=3072)
    mma_gemm<false><<<dim3(SEQ / 128, SEQ / 128, BATCH), 256, SMEM_B>>>(
        QA, KB, nullptr, sc, 3 * EMBED, SEQ,
        (long long)SEQ * 3 * EMBED, (long long)SEQ * 3 * EMBED, (long long)SEQ * SEQ,
        0.03125f);

    // softmax + split -> PA
    softmax_pa_kernel<<<BATCH * SEQ, 256>>>(sc, PA);

    // GEMM3: out = P @ V   (per batch M=2048, N=1024, Keff=6144)
    mma_gemm<false><<<dim3(EMBED / 128, SEQ / 128, BATCH), 256, SMEM_B>>>(
        PA, VB, nullptr, out, 3 * SEQ, EMBED,
        (long long)SEQ * 3 * SEQ, (long long)EMBED * 3 * SEQ, (long long)SEQ * EMBED,
        1.0f);
}

// round 4
// speedup vs baseline: 1.9362x; 1.0454x over previous
#include <cuda_runtime.h>
#include <cuda_bf16.h>
#include <math.h>
#include <stdint.h>

#define BATCH   8
#define SEQ     2048
#define EMBED   1024
#define QKVD    3072

// ---------------- scratch (device globals; no allocs allowed) ---------------
__device__ float         g_V     [(size_t)BATCH * SEQ * EMBED];   // 67 MB fp32 V
__device__ float         g_scores[(size_t)BATCH * SEQ * SEQ];
__device__ __nv_bfloat16 g_A1[(size_t)BATCH * SEQ * (3*EMBED)];   // x split  (A-order)
__device__ __nv_bfloat16 g_B1[(size_t)QKVD * (3*EMBED)];          // W split  (B-order)
__device__ __nv_bfloat16 g_QA[(size_t)BATCH * SEQ * (3*EMBED)];   // Q split  (A-order)
__device__ __nv_bfloat16 g_KB[(size_t)BATCH * SEQ * (3*EMBED)];   // K split  (B-order)
__device__ __nv_bfloat16 g_VB[(size_t)BATCH * EMBED * (3*SEQ)];   // V^T split (B-order)
__device__ __nv_bfloat16 g_PA[(size_t)BATCH * SEQ * (3*SEQ)];     // probs split (A-order)

// ---------------- asm helpers ------------------------------------------------
__device__ __forceinline__ uint32_t smem_u32(const void* p) {
    uint32_t a;
    asm("{ .reg .u64 t; cvta.to.shared.u64 t, %1; cvt.u32.u64 %0, t; }" : "=r"(a) : "l"(p));
    return a;
}
#define CP_ASYNC16(dst, src) \
    asm volatile("cp.async.cg.shared.global [%0], [%1], 16;" :: "r"(dst), "l"(src))
#define CP_COMMIT() asm volatile("cp.async.commit_group;" ::: "memory")
#define CP_WAIT2()  asm volatile("cp.async.wait_group 2;"  ::: "memory")
#define LDMX4(r, addr) \
    asm volatile("ldmatrix.sync.aligned.m8n8.x4.shared.b16 {%0,%1,%2,%3}, [%4];" \
        : "=r"((r)[0]), "=r"((r)[1]), "=r"((r)[2]), "=r"((r)[3]) : "r"(addr))
#define MMA16816(d, a, b) \
    asm volatile("mma.sync.aligned.m16n8k16.row.col.f32.bf16.bf16.f32 " \
        "{%0,%1,%2,%3}, {%4,%5,%6,%7}, {%8,%9}, {%0,%1,%2,%3};" \
        : "+f"((d)[0]), "+f"((d)[1]), "+f"((d)[2]), "+f"((d)[3]) \
        : "r"((a)[0]), "r"((a)[1]), "r"((a)[2]), "r"((a)[3]), "r"((b)[0]), "r"((b)[1]))

// ---------------- tensor-core GEMM -------------------------------------------
// C[m,n] = alpha * sum_k A[m,k] B[n,k]  (A, B row-major bf16, K-major)
// Block tile 128x128, K-chunk 64, 3-stage cp.async pipeline.
// 256 threads = 8 warps (2m x 4n), warp tile 64x32, mma.m16n8k16 bf16->fp32.
// MODE 0: plain epilogue (alpha scale) -> fp32 C
// MODE 1: fused qkv epilogue: bias add, then per-region split:
//         cols [0,1024)  -> QA  [row,3E] hi|lo|hi
//         cols [1024,2048)-> KB [row,3E] hi|hi|lo
//         cols [2048,3072)-> Vf fp32 [row,1024]
#define LDT     72                       // smem row pitch in halves (144 B)
#define ATILE_H (128 * LDT)
#define BUF_H   (2 * ATILE_H)            // A+B tile per stage (halves)
#define NSTAGE  3
#define SMEM_B  (NSTAGE * BUF_H * 2)     // 110592 bytes

__device__ __forceinline__ void load_chunk(uint32_t sb, int stage,
    const __nv_bfloat16* __restrict__ Ag, const __nv_bfloat16* __restrict__ Bg,
    int K, int k0, int tid)
{
    const int r = tid >> 1;
    const int c = (tid & 1) * 32;
    const uint32_t base = sb + (uint32_t)stage * (BUF_H * 2) + (r * LDT + c) * 2;
    const __nv_bfloat16* as = Ag + (size_t)r * K + k0 + c;
    const __nv_bfloat16* bs = Bg + (size_t)r * K + k0 + c;
    #pragma unroll
    for (int i = 0; i < 4; ++i) CP_ASYNC16(base + i * 16, as + i * 8);
    #pragma unroll
    for (int i = 0; i < 4; ++i) CP_ASYNC16(base + ATILE_H * 2 + i * 16, bs + i * 8);
}

template<int MODE>
__global__ void __launch_bounds__(256, 2) mma_gemm(
    const __nv_bfloat16* __restrict__ A, const __nv_bfloat16* __restrict__ B,
    const float* __restrict__ bias, float* __restrict__ C,
    __nv_bfloat16* __restrict__ QA, __nv_bfloat16* __restrict__ KB,
    float* __restrict__ Vf,
    int K, int ldc, long long sA, long long sB, long long sC, float alpha)
{
    extern __shared__ char smem[];
    const uint32_t sb = smem_u32(smem);
    const int tid = threadIdx.x;
    const int lane = tid & 31;
    const int wid = tid >> 5;
    const int wm = (wid & 1) * 64;
    const int wn = (wid >> 1) * 32;

    const __nv_bfloat16* Ag = A + blockIdx.z * sA + (size_t)(blockIdx.y * 128) * K;
    const __nv_bfloat16* Bg = B + blockIdx.z * sB + (size_t)(blockIdx.x * 128) * K;

    const int ar = (lane & 7) + ((lane >> 3) & 1) * 8;
    const int ak = (lane >> 4) * 8;
    const int bn = (lane & 7) + ((lane >> 4) & 1) * 8;
    const int bk = ((lane >> 3) & 1) * 8;

    float acc[4][4][4];
    #pragma unroll
    for (int i = 0; i < 4; ++i)
        #pragma unroll
        for (int j = 0; j < 4; ++j)
            #pragma unroll
            for (int q = 0; q < 4; ++q) acc[i][j][q] = 0.0f;

    const int nch = K / 64;
    load_chunk(sb, 0, Ag, Bg, K, 0, tid);   CP_COMMIT();
    load_chunk(sb, 1, Ag, Bg, K, 64, tid);  CP_COMMIT();
    load_chunk(sb, 2, Ag, Bg, K, 128, tid); CP_COMMIT();

    int stage = 0;
    for (int ch = 0; ch < nch; ++ch) {
        CP_WAIT2();
        __syncthreads();

        const uint32_t abase = sb + (uint32_t)stage * (BUF_H * 2);
        const uint32_t bbase = abase + ATILE_H * 2;
        #pragma unroll
        for (int s = 0; s < 4; ++s) {
            uint32_t a[4][4];
            #pragma unroll
            for (int mf = 0; mf < 4; ++mf)
                LDMX4(a[mf], abase + ((wm + mf * 16 + ar) * LDT + s * 16 + ak) * 2);
            uint32_t b[2][4];
            #pragma unroll
            for (int n2 = 0; n2 < 2; ++n2)
                LDMX4(b[n2], bbase + ((wn + n2 * 16 + bn) * LDT + s * 16 + bk) * 2);
            #pragma unroll
            for (int mf = 0; mf < 4; ++mf)
                #pragma unroll
                for (int nf = 0; nf < 4; ++nf)
                    MMA16816(acc[mf][nf], a[mf], &b[nf >> 1][(nf & 1) * 2]);
        }
        __syncthreads();
        if (ch + 3 < nch) load_chunk(sb, stage, Ag, Bg, K, (ch + 3) * 64, tid);
        CP_COMMIT();
        stage = (stage == NSTAGE - 1) ? 0 : stage + 1;
    }

    // ---------------- epilogue ----------------
    const int g  = lane >> 2;
    const int tg = lane & 3;

    if (MODE == 0) {
        float* Cg = C + blockIdx.z * sC;
        #pragma unroll
        for (int mf = 0; mf < 4; ++mf) {
            const int row0 = blockIdx.y * 128 + wm + mf * 16 + g;
            #pragma unroll
            for (int nf = 0; nf < 4; ++nf) {
                const int col = blockIdx.x * 128 + wn + nf * 8 + tg * 2;
                float2 v0 = make_float2(acc[mf][nf][0] * alpha, acc[mf][nf][1] * alpha);
                float2 v1 = make_float2(acc[mf][nf][2] * alpha, acc[mf][nf][3] * alpha);
                *reinterpret_cast<float2*>(Cg + (size_t)row0 * ldc + col) = v0;
                *reinterpret_cast<float2*>(Cg + (size_t)(row0 + 8) * ldc + col) = v1;
            }
        }
    } else {
        const int cblk = blockIdx.x * 128;           // global col of CTA slab
        const int region = cblk >> 10;               // 0=Q 1=K 2=V
        #pragma unroll
        for (int mf = 0; mf < 4; ++mf) {
            const int row0 = blockIdx.y * 128 + wm + mf * 16 + g;
            #pragma unroll
            for (int nf = 0; nf < 4; ++nf) {
                const int gcol = cblk + wn + nf * 8 + tg * 2;
                const float2 bb = *reinterpret_cast<const float2*>(bias + gcol);
                float v[2][2];
                v[0][0] = acc[mf][nf][0] + bb.x;  v[0][1] = acc[mf][nf][1] + bb.y;
                v[1][0] = acc[mf][nf][2] + bb.x;  v[1][1] = acc[mf][nf][3] + bb.y;
                const int lcol = gcol & 1023;        // col within region
                if (region == 2) {
                    *reinterpret_cast<float2*>(Vf + (size_t)row0 * EMBED + lcol)
                        = make_float2(v[0][0], v[0][1]);
                    *reinterpret_cast<float2*>(Vf + (size_t)(row0 + 8) * EMBED + lcol)
                        = make_float2(v[1][0], v[1][1]);
                } else {
                    __nv_bfloat16* dst = (region == 0) ? QA : KB;
                    #pragma unroll
                    for (int h = 0; h < 2; ++h) {
                        const int r = row0 + h * 8;
                        __nv_bfloat16 hi0 = __float2bfloat16(v[h][0]);
                        __nv_bfloat16 hi1 = __float2bfloat16(v[h][1]);
                        __nv_bfloat16 lo0 = __float2bfloat16(v[h][0] - __bfloat162float(hi0));
                        __nv_bfloat16 lo1 = __float2bfloat16(v[h][1] - __bfloat162float(hi1));
                        __nv_bfloat162 hp(hi0, hi1), lp(lo0, lo1);
                        __nv_bfloat16* d0 = dst + (size_t)r * (3 * EMBED) + lcol;
                        if (region == 0) {   // QA: hi | lo | hi
                            *reinterpret_cast<__nv_bfloat162*>(d0)             = hp;
                            *reinterpret_cast<__nv_bfloat162*>(d0 + EMBED)     = lp;
                            *reinterpret_cast<__nv_bfloat162*>(d0 + 2 * EMBED) = hp;
                        } else {             // KB: hi | hi | lo
                            *reinterpret_cast<__nv_bfloat162*>(d0)             = hp;
                            *reinterpret_cast<__nv_bfloat162*>(d0 + EMBED)     = hp;
                            *reinterpret_cast<__nv_bfloat162*>(d0 + 2 * EMBED) = lp;
                        }
                    }
                }
            }
        }
    }
}

// ---------------- fp32 -> bf16 hi/lo split (for x and W inputs) --------------
template<bool AORDER>
__global__ void split_kernel(const float* __restrict__ src, __nv_bfloat16* __restrict__ dst,
                             int K, int srcPitch, int srcOff, long long nvec)
{
    long long i = blockIdx.x * (long long)blockDim.x + threadIdx.x;
    if (i >= nvec) return;
    long long e = i * 4;
    int row = (int)(e / K), col = (int)(e % K);
    const float4 v = *reinterpret_cast<const float4*>(src + (size_t)row * srcPitch + srcOff + col);
    float vs[4] = { v.x, v.y, v.z, v.w };
    __nv_bfloat16 h[4], l[4];
    #pragma unroll
    for (int j = 0; j < 4; ++j) {
        h[j] = __float2bfloat16(vs[j]);
        l[j] = __float2bfloat16(vs[j] - __bfloat162float(h[j]));
    }
    __nv_bfloat162 hp0(h[0], h[1]), hp1(h[2], h[3]);
    __nv_bfloat162 lp0(l[0], l[1]), lp1(l[2], l[3]);
    __nv_bfloat16* d0 = dst + (size_t)row * 3 * K + col;
    reinterpret_cast<__nv_bfloat162*>(d0)[0] = hp0;
    reinterpret_cast<__nv_bfloat162*>(d0)[1] = hp1;
    if (AORDER) {
        reinterpret_cast<__nv_bfloat162*>(d0 + K)[0] = lp0;
        reinterpret_cast<__nv_bfloat162*>(d0 + K)[1] = lp1;
        reinterpret_cast<__nv_bfloat162*>(d0 + 2 * K)[0] = hp0;
        reinterpret_cast<__nv_bfloat162*>(d0 + 2 * K)[1] = hp1;
    } else {
        reinterpret_cast<__nv_bfloat162*>(d0 + K)[0] = hp0;
        reinterpret_cast<__nv_bfloat162*>(d0 + K)[1] = hp1;
        reinterpret_cast<__nv_bfloat162*>(d0 + 2 * K)[0] = lp0;
        reinterpret_cast<__nv_bfloat162*>(d0 + 2 * K)[1] = lp1;
    }
}

// ---------------- V transpose + split (B-order [hi|hi|lo]) -------------------
__global__ void vtrans_kernel(const float* __restrict__ Vf, __nv_bfloat16* __restrict__ VB)
{
    __shared__ float t[32][33];
    const int b = blockIdx.z;
    const int n0 = blockIdx.x * 32, e0 = blockIdx.y * 32;
    const int tx = threadIdx.x, ty = threadIdx.y;
    const float* src = Vf + (size_t)b * SEQ * EMBED;
    #pragma unroll
    for (int i = 0; i < 4; ++i)
        t[ty + 8 * i][tx] = src[(size_t)(n0 + ty + 8 * i) * EMBED + e0 + tx];
    __syncthreads();
    __nv_bfloat16* dst = VB + (size_t)b * EMBED * (3 * SEQ);
    #pragma unroll
    for (int i = 0; i < 4; ++i) {
        const float v = t[tx][ty + 8 * i];
        const __nv_bfloat16 h = __float2bfloat16(v);
        const __nv_bfloat16 l = __float2bfloat16(v - __bfloat162float(h));
        const size_t base = (size_t)(e0 + ty + 8 * i) * (3 * SEQ) + n0 + tx;
        dst[base]           = h;
        dst[base + SEQ]     = h;
        dst[base + 2 * SEQ] = l;
    }
}

// ---------------- softmax + prob split (A-order [hi|lo|hi]) ------------------
__global__ void softmax_pa_kernel(const float* __restrict__ s, __nv_bfloat16* __restrict__ PA)
{
    __shared__ float row[SEQ];
    __shared__ float red[8];
    const int tid = threadIdx.x;
    const float4* p4 = reinterpret_cast<const float4*>(s + (size_t)blockIdx.x * SEQ);
    float4* r4 = reinterpret_cast<float4*>(row);

    float lmax = -3.4e38f;
    #pragma unroll
    for (int it = 0; it < 2; ++it) {
        const float4 t = p4[tid + it * 256];
        r4[tid + it * 256] = t;
        lmax = fmaxf(lmax, fmaxf(fmaxf(t.x, t.y), fmaxf(t.z, t.w)));
    }
    #pragma unroll
    for (int o = 16; o; o >>= 1) lmax = fmaxf(lmax, __shfl_xor_sync(0xffffffffu, lmax, o));
    if ((tid & 31) == 0) red[tid >> 5] = lmax;
    __syncthreads();
    const float rmax = fmaxf(fmaxf(fmaxf(red[0], red[1]), fmaxf(red[2], red[3])),
                             fmaxf(fmaxf(red[4], red[5]), fmaxf(red[6], red[7])));
    __syncthreads();

    float lsum = 0.0f;
    #pragma unroll
    for (int it = 0; it < 2; ++it) {
        float4 t = r4[tid + it * 256];
        t.x = expf(t.x - rmax); t.y = expf(t.y - rmax);
        t.z = expf(t.z - rmax); t.w = expf(t.w - rmax);
        r4[tid + it * 256] = t;
        lsum += (t.x + t.y) + (t.z + t.w);
    }
    #pragma unroll
    for (int o = 16; o; o >>= 1) lsum += __shfl_xor_sync(0xffffffffu, lsum, o);
    if ((tid & 31) == 0) red[tid >> 5] = lsum;
    __syncthreads();
    const float inv = 1.0f / (((red[0] + red[1]) + (red[2] + red[3])) +
                              ((red[4] + red[5]) + (red[6] + red[7])));

    __nv_bfloat16* pa = PA + (size_t)blockIdx.x * (3 * SEQ);
    #pragma unroll
    for (int it = 0; it < 2; ++it) {
        float4 t = r4[tid + it * 256];
        t.x *= inv; t.y *= inv; t.z *= inv; t.w *= inv;
        float vs[4] = { t.x, t.y, t.z, t.w };
        __nv_bfloat16 h[4], l[4];
        #pragma unroll
        for (int j = 0; j < 4; ++j) {
            h[j] = __float2bfloat16(vs[j]);
            l[j] = __float2bfloat16(vs[j] - __bfloat162float(h[j]));
        }
        const int idx = (tid + it * 256) * 4;
        __nv_bfloat162 hp0(h[0], h[1]), hp1(h[2], h[3]);
        __nv_bfloat162 lp0(l[0], l[1]), lp1(l[2], l[3]);
        reinterpret_cast<__nv_bfloat162*>(pa + idx)[0] = hp0;
        reinterpret_cast<__nv_bfloat162*>(pa + idx)[1] = hp1;
        reinterpret_cast<__nv_bfloat162*>(pa + SEQ + idx)[0] = lp0;
        reinterpret_cast<__nv_bfloat162*>(pa + SEQ + idx)[1] = lp1;
        reinterpret_cast<__nv_bfloat162*>(pa + 2 * SEQ + idx)[0] = hp0;
        reinterpret_cast<__nv_bfloat162*>(pa + 2 * SEQ + idx)[1] = hp1;
    }
}

// -----------------------------------------------------------------------------
extern "C" void kernel_launch(void* const* d_in, const int* in_sizes, int n_in,
                              void* d_out, int out_size)
{
    const float* x = (const float*)d_in[0];
    const float* W = (const float*)d_in[1];
    const float* b = (const float*)d_in[2];
    float* out = (float*)d_out;

    float *Vf, *sc;
    __nv_bfloat16 *A1, *B1, *QA, *KB, *VB, *PA;
    { void* p; cudaGetSymbolAddress(&p, g_V);      Vf = (float*)p; }
    { void* p; cudaGetSymbolAddress(&p, g_scores); sc = (float*)p; }
    { void* p; cudaGetSymbolAddress(&p, g_A1); A1 = (__nv_bfloat16*)p; }
    { void* p; cudaGetSymbolAddress(&p, g_B1); B1 = (__nv_bfloat16*)p; }
    { void* p; cudaGetSymbolAddress(&p, g_QA); QA = (__nv_bfloat16*)p; }
    { void* p; cudaGetSymbolAddress(&p, g_KB); KB = (__nv_bfloat16*)p; }
    { void* p; cudaGetSymbolAddress(&p, g_VB); VB = (__nv_bfloat16*)p; }
    { void* p; cudaGetSymbolAddress(&p, g_PA); PA = (__nv_bfloat16*)p; }

    cudaFuncSetAttribute(mma_gemm<0>, cudaFuncAttributeMaxDynamicSharedMemorySize, SMEM_B);
    cudaFuncSetAttribute(mma_gemm<1>, cudaFuncAttributeMaxDynamicSharedMemorySize, SMEM_B);

    const long long MN = (long long)BATCH * SEQ;   // 16384

    // input splits: x -> A1 (A-order), W -> B1 (B-order)
    split_kernel<true ><<<(unsigned)((MN * EMBED / 4 + 255) / 256), 256>>>(
        x, A1, EMBED, EMBED, 0, MN * EMBED / 4);
    split_kernel<false><<<(unsigned)(((long long)QKVD * EMBED / 4 + 255) / 256), 256>>>(
        W, B1, EMBED, EMBED, 0, (long long)QKVD * EMBED / 4);

    // GEMM1 (fused): qkv = x @ W^T + b, epilogue emits QA / KB / Vf directly
    mma_gemm<1><<<dim3(QKVD / 128, (unsigned)(MN / 128), 1), 256, SMEM_B>>>(
        A1, B1, b, nullptr, QA, KB, Vf,
        3 * EMBED, 0, 0, 0, 0, 1.0f);

    // V transpose + split
    vtrans_kernel<<<dim3(SEQ / 32, EMBED / 32, BATCH), dim3(32, 8)>>>(Vf, VB);

    // GEMM2: scores = Q @ K^T / 32   (per batch M=N=2048, Keff=3072)
    mma_gemm<0><<<dim3(SEQ / 128, SEQ / 128, BATCH), 256, SMEM_B>>>(
        QA, KB, nullptr, sc, nullptr, nullptr, nullptr,
        3 * EMBED, SEQ,
        (long long)SEQ * 3 * EMBED, (long long)SEQ * 3 * EMBED, (long long)SEQ * SEQ,
        0.03125f);

    // softmax + split -> PA
    softmax_pa_kernel<<<BATCH * SEQ, 256>>>(sc, PA);

    // GEMM3: out = P @ V   (per batch M=2048, N=1024, Keff=6144)
    mma_gemm<0><<<dim3(EMBED / 128, SEQ / 128, BATCH), 256, SMEM_B>>>(
        PA, VB, nullptr, out, nullptr, nullptr, nullptr,
        3 * SEQ, EMBED,
        (long long)SEQ * 3 * SEQ, (long long)EMBED * 3 * SEQ, (long long)SEQ * EMBED,
        1.0f);
}